// round 1
// baseline (speedup 1.0000x reference)
#include <cuda_runtime.h>
#include <math.h>

// ---------------- problem constants ----------------
#define NN    50000
#define HH    128
#define EE    1000000
#define FF1   147
#define FF2   21
#define MM    64
#define GG    512
#define OUTC  128
#define EPSV  1e-5f

// ---------------- device scratch (no allocs allowed) ----------------
__device__ float g_xh  [NN*HH];
__device__ float g_agg1[NN*HH];
__device__ float g_agg2[NN*HH];
__device__ float g_tmp [NN*HH];
__device__ float g_h1  [NN*HH];
__device__ float g_h2  [NN*HH];
__device__ float g_hA  [NN*HH];
__device__ float g_hB  [NN*HH];
__device__ float g_gsum[GG*HH];
__device__ float g_gvar[GG*HH];
__device__ float g_gcnt[GG];

// ---------------- zero init ----------------
__global__ void zero_bufs_kernel() {
    int idx = blockIdx.x * blockDim.x + threadIdx.x;
    if (idx < NN*HH) { g_agg1[idx] = 0.f; g_agg2[idx] = 0.f; }
    if (idx < GG*HH) { g_gsum[idx] = 0.f; g_gvar[idx] = 0.f; }
    if (idx < GG)    { g_gcnt[idx] = 0.f; }
}

// ---------------- generic node GEMM ----------------
// out[n,c] = epilogue( sum_k A[n,k]*W[k,c] (+ sum_k A2[n,k]*W2[k,c]) + bias[c] )
// epilogue: optional swish, optional +res[n,c].
// 256 threads, 16 rows per block (2 groups x 8 rows register tile).
// W (and W2) staged to SMEM; rows staged transposed with stride 20 (pad for banks,
// 16B-aligned for float4 broadcast loads).
template<bool HAS_A2, bool ACT, bool HAS_RES>
__global__ void __launch_bounds__(256) node_gemm(
    const float* __restrict__ A,  const float* __restrict__ W,
    const float* __restrict__ A2, const float* __restrict__ W2,
    const float* __restrict__ bias, const float* __restrict__ res,
    float* __restrict__ out, int nrows)
{
    extern __shared__ float sm[];
    float* sW  = sm;                                   // 16384
    float* sW2 = HAS_A2 ? sm + 16384 : (float*)0;      // 16384 if A2
    float* rT  = sm + (HAS_A2 ? 32768 : 16384);        // 128*20
    float* rT2 = HAS_A2 ? rT + 128*20 : (float*)0;     // 128*20 if A2

    const int tid = threadIdx.x;
    for (int i = tid; i < 16384; i += 256) {
        sW[i] = W[i];
        if (HAS_A2) sW2[i] = W2[i];
    }
    const int row_base = blockIdx.x * 16;
    for (int idx = tid; idx < 16*128; idx += 256) {
        int node = idx >> 7, k = idx & 127;
        int r = row_base + node;
        rT[k*20 + node] = (r < nrows) ? A[(size_t)r*128 + k] : 0.f;
        if (HAS_A2) rT2[k*20 + node] = (r < nrows) ? A2[(size_t)r*128 + k] : 0.f;
    }
    __syncthreads();

    const int c = tid & 127;
    const int g = tid >> 7;          // 0..1, constant within a warp
    float acc[8] = {0,0,0,0,0,0,0,0};

    #pragma unroll 4
    for (int k = 0; k < 128; ++k) {
        float w = sW[k*128 + c];
        float4 a0 = *reinterpret_cast<const float4*>(&rT[k*20 + g*8]);
        float4 a1 = *reinterpret_cast<const float4*>(&rT[k*20 + g*8 + 4]);
        acc[0] += a0.x*w; acc[1] += a0.y*w; acc[2] += a0.z*w; acc[3] += a0.w*w;
        acc[4] += a1.x*w; acc[5] += a1.y*w; acc[6] += a1.z*w; acc[7] += a1.w*w;
        if (HAS_A2) {
            float w2 = sW2[k*128 + c];
            float4 b0 = *reinterpret_cast<const float4*>(&rT2[k*20 + g*8]);
            float4 b1 = *reinterpret_cast<const float4*>(&rT2[k*20 + g*8 + 4]);
            acc[0] += b0.x*w2; acc[1] += b0.y*w2; acc[2] += b0.z*w2; acc[3] += b0.w*w2;
            acc[4] += b1.x*w2; acc[5] += b1.y*w2; acc[6] += b1.z*w2; acc[7] += b1.w*w2;
        }
    }

    const float bv = bias[c];
    #pragma unroll
    for (int i = 0; i < 8; ++i) {
        int r = row_base + g*8 + i;
        if (r < nrows) {
            float v = acc[i] + bv;
            if (ACT) v = v / (1.f + expf(-v));
            if (HAS_RES) v += res[(size_t)r*128 + c];
            out[(size_t)r*128 + c] = v;
        }
    }
}

// ---------------- fused edge kernel ----------------
// per edge e: mid[64] = feat[e,:] @ w1 ; o[128] = mid @ w2 ;
//             agg[dst[e], c] += o[c] * xh[src[e], c]
// 128 threads/block; weights resident in SMEM; grid-stride over edges.
template<int F>
__global__ void __launch_bounds__(128) edge_msg(
    const float* __restrict__ feat, const float* __restrict__ w1,
    const float* __restrict__ w2,   const float* __restrict__ xh,
    const int* __restrict__ src,    const int* __restrict__ dst,
    float* __restrict__ agg)
{
    extern __shared__ float sm[];
    float* sw1   = sm;                     // F*64
    float* sw2   = sw1 + F*64;             // 64*128
    float* sfeat = sw2 + 64*128;           // F (padded to mult of 4)
    float* part  = sfeat + ((F+3)&~3);     // 128
    float* smid  = part + 128;             // 64

    const int tid = threadIdx.x;
    for (int i = tid; i < F*64; i += 128)   sw1[i] = w1[i];
    for (int i = tid; i < 64*128; i += 128) sw2[i] = w2[i];
    __syncthreads();

    const int j    = tid & 63;
    const int half = tid >> 6;
    const int k0   = half ? (F/2) : 0;
    const int k1   = half ? F : (F/2);

    for (int e = blockIdx.x; e < EE; e += gridDim.x) {
        for (int i = tid; i < F; i += 128) sfeat[i] = feat[(size_t)e*F + i];
        __syncthreads();

        float a = 0.f;
        for (int k = k0; k < k1; ++k) a += sfeat[k] * sw1[k*64 + j];
        part[tid] = a;
        __syncthreads();

        if (tid < 64) smid[tid] = part[tid] + part[tid + 64];
        __syncthreads();

        float o = 0.f;
        #pragma unroll
        for (int k = 0; k < 64; ++k) o += smid[k] * sw2[k*128 + tid];

        const int s = src[e], d = dst[e];
        float v = o * xh[((size_t)s << 7) + tid];
        atomicAdd(&agg[((size_t)d << 7) + tid], v);
        __syncthreads();   // protect sfeat/part/smid for next iteration
    }
}

// ---------------- GraphNorm kernels ----------------
__global__ void gn_accum(const float* __restrict__ h, const int* __restrict__ batch) {
    int idx = blockIdx.x * blockDim.x + threadIdx.x;
    if (idx >= NN*HH) return;
    int n = idx >> 7, c = idx & 127;
    int b = batch[n];
    atomicAdd(&g_gsum[b*128 + c], h[idx]);
    if (c == 0) atomicAdd(&g_gcnt[b], 1.f);
}

__global__ void gn_mean() {
    int idx = blockIdx.x * blockDim.x + threadIdx.x;
    if (idx >= GG*HH) return;
    int g = idx >> 7;
    g_gsum[idx] /= fmaxf(g_gcnt[g], 1.f);
}

__global__ void gn_center(const float* __restrict__ h, const int* __restrict__ batch,
                          const float* __restrict__ ms, float* __restrict__ out) {
    int idx = blockIdx.x * blockDim.x + threadIdx.x;
    if (idx >= NN*HH) return;
    int n = idx >> 7, c = idx & 127;
    int b = batch[n];
    float o = h[idx] - g_gsum[b*128 + c] * ms[c];
    out[idx] = o;
    atomicAdd(&g_gvar[b*128 + c], o*o);
}

__global__ void gn_inv() {
    int idx = blockIdx.x * blockDim.x + threadIdx.x;
    if (idx >= GG*HH) return;
    int g = idx >> 7;
    g_gvar[idx] = rsqrtf(g_gvar[idx] / fmaxf(g_gcnt[g], 1.f) + EPSV);
}

__global__ void gn_apply(const float* __restrict__ cent, const int* __restrict__ batch,
                         const float* __restrict__ nw, const float* __restrict__ nb,
                         float* __restrict__ out) {
    int idx = blockIdx.x * blockDim.x + threadIdx.x;
    if (idx >= NN*HH) return;
    int n = idx >> 7, c = idx & 127;
    int b = batch[n];
    out[idx] = nw[c] * cent[idx] * g_gvar[b*128 + c] + nb[c];
}

// ---------------- host launcher ----------------
static inline void set_smem(const void* f, int bytes) {
    cudaFuncSetAttribute(f, cudaFuncAttributeMaxDynamicSharedMemorySize, bytes);
}

extern "C" void kernel_launch(void* const* d_in, const int* in_sizes, int n_in,
                              void* d_out, int out_size) {
    (void)in_sizes; (void)n_in; (void)out_size;

    const float* x          = (const float*)d_in[0];
    const float* feature1   = (const float*)d_in[1];
    const float* feature2   = (const float*)d_in[2];
    const int*   edge_index = (const int*)  d_in[3];
    const int*   batch      = (const int*)  d_in[4];
    const float* lin_w      = (const float*)d_in[5];
    const float* lin_b      = (const float*)d_in[6];
    const float* f1_w1      = (const float*)d_in[7];
    const float* f1_w2      = (const float*)d_in[8];
    const float* f2_w1      = (const float*)d_in[9];
    const float* f2_w2      = (const float*)d_in[10];
    const float* c1_rel_w   = (const float*)d_in[11];
    const float* c1_rel_b   = (const float*)d_in[12];
    const float* c1_root_w  = (const float*)d_in[13];
    const float* c2_rel_w   = (const float*)d_in[14];
    const float* c2_rel_b   = (const float*)d_in[15];
    const float* c2_root_w  = (const float*)d_in[16];
    const float* lin1_w     = (const float*)d_in[17];
    const float* lin1_b     = (const float*)d_in[18];
    const float* lin2_w     = (const float*)d_in[19];
    const float* lin2_b     = (const float*)d_in[20];
    const float* lincat_w   = (const float*)d_in[21];
    const float* lincat_b   = (const float*)d_in[22];
    const float* norm_w     = (const float*)d_in[23];
    const float* norm_b     = (const float*)d_in[24];
    const float* norm_ms    = (const float*)d_in[25];
    const float* lins_w     = (const float*)d_in[26];
    const float* lins_b     = (const float*)d_in[27];
    const float* final_w    = (const float*)d_in[28];
    const float* final_b    = (const float*)d_in[29];
    float* out = (float*)d_out;

    const int* src = edge_index;        // edge_index[0, :]
    const int* dst = edge_index + EE;   // edge_index[1, :]

    float *xh, *agg1, *agg2, *tmp, *h1, *h2, *hA, *hB;
    cudaGetSymbolAddress((void**)&xh,   g_xh);
    cudaGetSymbolAddress((void**)&agg1, g_agg1);
    cudaGetSymbolAddress((void**)&agg2, g_agg2);
    cudaGetSymbolAddress((void**)&tmp,  g_tmp);
    cudaGetSymbolAddress((void**)&h1,   g_h1);
    cudaGetSymbolAddress((void**)&h2,   g_h2);
    cudaGetSymbolAddress((void**)&hA,   g_hA);
    cudaGetSymbolAddress((void**)&hB,   g_hB);

    // dynamic smem sizes
    const int NG1  = (16384 + 128*20) * 4;           // 73.0 KB  (single A)
    const int NG2  = (32768 + 2*128*20) * 4;         // 148  KB  (A + A2)
    const int E147 = (FF1*64 + 64*128 + ((FF1+3)&~3) + 128 + 64) * 4;
    const int E21  = (FF2*64 + 64*128 + ((FF2+3)&~3) + 128 + 64) * 4;

    set_smem((const void*)node_gemm<false,true ,false>, NG1);
    set_smem((const void*)node_gemm<false,true ,true >, NG1);
    set_smem((const void*)node_gemm<false,false,false>, NG1);
    set_smem((const void*)node_gemm<true ,false,false>, NG2);
    set_smem((const void*)node_gemm<true ,false,true >, NG2);
    set_smem((const void*)edge_msg<FF1>, E147);
    set_smem((const void*)edge_msg<FF2>, E21);

    const int NG_GRID = (NN + 15) / 16;     // 3125
    const int EL_GRID = (NN*HH + 255) / 256;
    const int GH_GRID = (GG*HH + 255) / 256;

    // 0) zero accumulators
    zero_bufs_kernel<<<EL_GRID, 256>>>();

    // 1) xh = swish(x @ lin_w + lin_b)
    node_gemm<false,true,false><<<NG_GRID, 256, NG1>>>(
        x, lin_w, nullptr, nullptr, lin_b, nullptr, xh, NN);

    // 2) edge messages + scatter-add
    edge_msg<FF1><<<444, 128, E147>>>(feature1, f1_w1, f1_w2, xh, src, dst, agg1);
    edge_msg<FF2><<<740, 128, E21 >>>(feature2, f2_w1, f2_w2, xh, src, dst, agg2);

    // 3) conv1: tmp = agg1@rel + xh@root + rel_b ; h1 = swish(tmp@lin1 + b1)
    node_gemm<true,false,false><<<NG_GRID, 256, NG2>>>(
        agg1, c1_rel_w, xh, c1_root_w, c1_rel_b, nullptr, tmp, NN);
    node_gemm<false,true,false><<<NG_GRID, 256, NG1>>>(
        tmp, lin1_w, nullptr, nullptr, lin1_b, nullptr, h1, NN);

    // 4) conv2
    node_gemm<true,false,false><<<NG_GRID, 256, NG2>>>(
        agg2, c2_rel_w, xh, c2_root_w, c2_rel_b, nullptr, tmp, NN);
    node_gemm<false,true,false><<<NG_GRID, 256, NG1>>>(
        tmp, lin2_w, nullptr, nullptr, lin2_b, nullptr, h2, NN);

    // 5) hA = h1@Wtop + h2@Wbot + lincat_b + xh
    node_gemm<true,false,true><<<NG_GRID, 256, NG2>>>(
        h1, lincat_w, h2, lincat_w + 128*128, lincat_b, xh, hA, NN);

    // 6) residual stack: h = swish(h@Wi + bi) + h   (x3)
    node_gemm<false,true,true><<<NG_GRID, 256, NG1>>>(
        hA, lins_w + 0*16384, nullptr, nullptr, lins_b + 0*128, hA, hB, NN);
    node_gemm<false,true,true><<<NG_GRID, 256, NG1>>>(
        hB, lins_w + 1*16384, nullptr, nullptr, lins_b + 1*128, hB, hA, NN);
    node_gemm<false,true,true><<<NG_GRID, 256, NG1>>>(
        hA, lins_w + 2*16384, nullptr, nullptr, lins_b + 2*128, hA, hB, NN);

    // 7) GraphNorm on hB
    gn_accum <<<EL_GRID, 256>>>(hB, batch);
    gn_mean  <<<GH_GRID, 256>>>();
    gn_center<<<EL_GRID, 256>>>(hB, batch, norm_ms, h1);   // h1 := centered
    gn_inv   <<<GH_GRID, 256>>>();
    gn_apply <<<EL_GRID, 256>>>(h1, batch, norm_w, norm_b, hA);

    // 8) out = hA @ final_w + final_b
    node_gemm<false,false,false><<<NG_GRID, 256, NG1>>>(
        hA, final_w, nullptr, nullptr, final_b, nullptr, out, NN);
}

// round 2
// speedup vs baseline: 2.0328x; 2.0328x over previous
#include <cuda_runtime.h>
#include <math.h>

// ---------------- problem constants ----------------
#define NN    50000
#define HH    128
#define EE    1000000
#define FF1   147
#define FF2   21
#define MM    64
#define GG    512
#define OUTC  128
#define EPSV  1e-5f

// ---------------- device scratch (no allocs allowed) ----------------
__device__ float g_xh  [NN*HH];
__device__ float g_agg1[NN*HH];
__device__ float g_agg2[NN*HH];
__device__ float g_tmp [NN*HH];
__device__ float g_h1  [NN*HH];
__device__ float g_h2  [NN*HH];
__device__ float g_hA  [NN*HH];
__device__ float g_hB  [NN*HH];
__device__ float g_gsum[GG*HH];
__device__ float g_gvar[GG*HH];
__device__ float g_gcnt[GG];

// ---------------- zero init ----------------
__global__ void zero_bufs_kernel() {
    int idx = blockIdx.x * blockDim.x + threadIdx.x;
    if (idx < NN*HH) { g_agg1[idx] = 0.f; g_agg2[idx] = 0.f; }
    if (idx < GG*HH) { g_gsum[idx] = 0.f; g_gvar[idx] = 0.f; }
    if (idx < GG)    { g_gcnt[idx] = 0.f; }
}

// ---------------- generic node GEMM ----------------
// out[n,c] = epilogue( sum_k A[n,k]*W[k,c] (+ sum_k A2[n,k]*W2[k,c]) + bias[c] )
template<bool HAS_A2, bool ACT, bool HAS_RES>
__global__ void __launch_bounds__(256) node_gemm(
    const float* __restrict__ A,  const float* __restrict__ W,
    const float* __restrict__ A2, const float* __restrict__ W2,
    const float* __restrict__ bias, const float* __restrict__ res,
    float* __restrict__ out, int nrows)
{
    extern __shared__ float sm[];
    float* sW  = sm;                                   // 16384
    float* sW2 = HAS_A2 ? sm + 16384 : (float*)0;      // 16384 if A2
    float* rT  = sm + (HAS_A2 ? 32768 : 16384);        // 128*20
    float* rT2 = HAS_A2 ? rT + 128*20 : (float*)0;     // 128*20 if A2

    const int tid = threadIdx.x;
    for (int i = tid; i < 16384; i += 256) {
        sW[i] = W[i];
        if (HAS_A2) sW2[i] = W2[i];
    }
    const int row_base = blockIdx.x * 16;
    for (int idx = tid; idx < 16*128; idx += 256) {
        int node = idx >> 7, k = idx & 127;
        int r = row_base + node;
        rT[k*20 + node] = (r < nrows) ? A[(size_t)r*128 + k] : 0.f;
        if (HAS_A2) rT2[k*20 + node] = (r < nrows) ? A2[(size_t)r*128 + k] : 0.f;
    }
    __syncthreads();

    const int c = tid & 127;
    const int g = tid >> 7;          // 0..1, constant within a warp
    float acc[8] = {0,0,0,0,0,0,0,0};

    #pragma unroll 4
    for (int k = 0; k < 128; ++k) {
        float w = sW[k*128 + c];
        float4 a0 = *reinterpret_cast<const float4*>(&rT[k*20 + g*8]);
        float4 a1 = *reinterpret_cast<const float4*>(&rT[k*20 + g*8 + 4]);
        acc[0] += a0.x*w; acc[1] += a0.y*w; acc[2] += a0.z*w; acc[3] += a0.w*w;
        acc[4] += a1.x*w; acc[5] += a1.y*w; acc[6] += a1.z*w; acc[7] += a1.w*w;
        if (HAS_A2) {
            float w2 = sW2[k*128 + c];
            float4 b0 = *reinterpret_cast<const float4*>(&rT2[k*20 + g*8]);
            float4 b1 = *reinterpret_cast<const float4*>(&rT2[k*20 + g*8 + 4]);
            acc[0] += b0.x*w2; acc[1] += b0.y*w2; acc[2] += b0.z*w2; acc[3] += b0.w*w2;
            acc[4] += b1.x*w2; acc[5] += b1.y*w2; acc[6] += b1.z*w2; acc[7] += b1.w*w2;
        }
    }

    const float bv = bias[c];
    #pragma unroll
    for (int i = 0; i < 8; ++i) {
        int r = row_base + g*8 + i;
        if (r < nrows) {
            float v = acc[i] + bv;
            if (ACT) v = v / (1.f + expf(-v));
            if (HAS_RES) v += res[(size_t)r*128 + c];
            out[(size_t)r*128 + c] = v;
        }
    }
}

// ---------------- fused edge kernel, register-blocked ----------------
// Tile of 32 edges per iteration.
//   GEMM1: mid[32,64] = feat[32,F] @ w1[F,64]      (256 thr = 64 cols x 4 row-groups of 8)
//   GEMM2: o[32,128]  = mid[32,64] @ w2[64,128]    (256 thr = 128 cols x 2 row-groups of 16)
//   epi:   agg[dst[e],c] += o[e,c] * xh[src[e],c]
template<int F>
__global__ void __launch_bounds__(256) edge_msg2(
    const float* __restrict__ feat, const float* __restrict__ w1,
    const float* __restrict__ w2,   const float* __restrict__ xh,
    const int* __restrict__ src,    const int* __restrict__ dst,
    float* __restrict__ agg, int ntiles)
{
    extern __shared__ float sm[];
    float* sw1 = sm;                    // F*64
    float* sw2 = sw1 + F*64;            // 64*128 = 8192
    float* sfT = sw2 + 8192;            // F*36   (feat tile, transposed, padded)
    float* smT = sfT + F*36;            // 64*36  (mid tile, transposed, padded)
    int*  sidx = (int*)(smT + 64*36);   // 64     (src[0..31], dst[0..31])

    const int tid = threadIdx.x;
    for (int i = tid; i < F*64; i += 256) sw1[i] = w1[i];
    for (int i = tid; i < 8192; i += 256) sw2[i] = w2[i];
    __syncthreads();

    for (int t = blockIdx.x; t < ntiles; t += gridDim.x) {
        const int e0 = t * 32;

        // stage feat tile transposed: sfT[k][e] = feat[e0+e][k]  (coalesced gmem reads)
        for (int i = tid; i < 32*F; i += 256) {
            int e = i / F, k = i - e*F;
            sfT[k*36 + e] = feat[(size_t)(e0+e)*F + k];
        }
        if (tid < 32) { sidx[tid] = src[e0+tid]; sidx[32+tid] = dst[e0+tid]; }
        __syncthreads();

        // ---- GEMM1 ----
        {
            const int j = tid & 63;      // mid column
            const int g = tid >> 6;      // 0..3 -> rows g*8..g*8+7
            float acc[8] = {0,0,0,0,0,0,0,0};
            #pragma unroll 7
            for (int k = 0; k < F; ++k) {
                float w = sw1[k*64 + j];
                float4 a0 = *reinterpret_cast<const float4*>(&sfT[k*36 + g*8]);
                float4 a1 = *reinterpret_cast<const float4*>(&sfT[k*36 + g*8 + 4]);
                acc[0] += a0.x*w; acc[1] += a0.y*w; acc[2] += a0.z*w; acc[3] += a0.w*w;
                acc[4] += a1.x*w; acc[5] += a1.y*w; acc[6] += a1.z*w; acc[7] += a1.w*w;
            }
            #pragma unroll
            for (int i = 0; i < 8; ++i) smT[j*36 + g*8 + i] = acc[i];
        }
        __syncthreads();

        // ---- GEMM2 + epilogue ----
        {
            const int c = tid & 127;     // output column
            const int g = tid >> 7;      // 0..1 -> rows g*16..g*16+15
            float acc[16];
            #pragma unroll
            for (int i = 0; i < 16; ++i) acc[i] = 0.f;
            #pragma unroll 8
            for (int k = 0; k < 64; ++k) {
                float w = sw2[k*128 + c];
                const float* mrow = &smT[k*36 + g*16];
                float4 m0 = *reinterpret_cast<const float4*>(mrow);
                float4 m1 = *reinterpret_cast<const float4*>(mrow + 4);
                float4 m2 = *reinterpret_cast<const float4*>(mrow + 8);
                float4 m3 = *reinterpret_cast<const float4*>(mrow + 12);
                acc[0]  += m0.x*w; acc[1]  += m0.y*w; acc[2]  += m0.z*w; acc[3]  += m0.w*w;
                acc[4]  += m1.x*w; acc[5]  += m1.y*w; acc[6]  += m1.z*w; acc[7]  += m1.w*w;
                acc[8]  += m2.x*w; acc[9]  += m2.y*w; acc[10] += m2.z*w; acc[11] += m2.w*w;
                acc[12] += m3.x*w; acc[13] += m3.y*w; acc[14] += m3.z*w; acc[15] += m3.w*w;
            }
            #pragma unroll
            for (int i = 0; i < 16; ++i) {
                int e = g*16 + i;
                int s = sidx[e], d = sidx[32 + e];
                float v = acc[i] * xh[((size_t)s << 7) + c];
                atomicAdd(&agg[((size_t)d << 7) + c], v);
            }
        }
        __syncthreads();   // protect sfT/smT/sidx for next tile
    }
}

// ---------------- GraphNorm kernels ----------------
__global__ void gn_accum(const float* __restrict__ h, const int* __restrict__ batch) {
    int idx = blockIdx.x * blockDim.x + threadIdx.x;
    if (idx >= NN*HH) return;
    int n = idx >> 7, c = idx & 127;
    int b = batch[n];
    atomicAdd(&g_gsum[b*128 + c], h[idx]);
    if (c == 0) atomicAdd(&g_gcnt[b], 1.f);
}

__global__ void gn_mean() {
    int idx = blockIdx.x * blockDim.x + threadIdx.x;
    if (idx >= GG*HH) return;
    int g = idx >> 7;
    g_gsum[idx] /= fmaxf(g_gcnt[g], 1.f);
}

__global__ void gn_center(const float* __restrict__ h, const int* __restrict__ batch,
                          const float* __restrict__ ms, float* __restrict__ out) {
    int idx = blockIdx.x * blockDim.x + threadIdx.x;
    if (idx >= NN*HH) return;
    int n = idx >> 7, c = idx & 127;
    int b = batch[n];
    float o = h[idx] - g_gsum[b*128 + c] * ms[c];
    out[idx] = o;
    atomicAdd(&g_gvar[b*128 + c], o*o);
}

__global__ void gn_inv() {
    int idx = blockIdx.x * blockDim.x + threadIdx.x;
    if (idx >= GG*HH) return;
    int g = idx >> 7;
    g_gvar[idx] = rsqrtf(g_gvar[idx] / fmaxf(g_gcnt[g], 1.f) + EPSV);
}

__global__ void gn_apply(const float* __restrict__ cent, const int* __restrict__ batch,
                         const float* __restrict__ nw, const float* __restrict__ nb,
                         float* __restrict__ out) {
    int idx = blockIdx.x * blockDim.x + threadIdx.x;
    if (idx >= NN*HH) return;
    int n = idx >> 7, c = idx & 127;
    int b = batch[n];
    out[idx] = nw[c] * cent[idx] * g_gvar[b*128 + c] + nb[c];
}

// ---------------- host launcher ----------------
static inline void set_smem(const void* f, int bytes) {
    cudaFuncSetAttribute(f, cudaFuncAttributeMaxDynamicSharedMemorySize, bytes);
}

extern "C" void kernel_launch(void* const* d_in, const int* in_sizes, int n_in,
                              void* d_out, int out_size) {
    (void)in_sizes; (void)n_in; (void)out_size;

    const float* x          = (const float*)d_in[0];
    const float* feature1   = (const float*)d_in[1];
    const float* feature2   = (const float*)d_in[2];
    const int*   edge_index = (const int*)  d_in[3];
    const int*   batch      = (const int*)  d_in[4];
    const float* lin_w      = (const float*)d_in[5];
    const float* lin_b      = (const float*)d_in[6];
    const float* f1_w1      = (const float*)d_in[7];
    const float* f1_w2      = (const float*)d_in[8];
    const float* f2_w1      = (const float*)d_in[9];
    const float* f2_w2      = (const float*)d_in[10];
    const float* c1_rel_w   = (const float*)d_in[11];
    const float* c1_rel_b   = (const float*)d_in[12];
    const float* c1_root_w  = (const float*)d_in[13];
    const float* c2_rel_w   = (const float*)d_in[14];
    const float* c2_rel_b   = (const float*)d_in[15];
    const float* c2_root_w  = (const float*)d_in[16];
    const float* lin1_w     = (const float*)d_in[17];
    const float* lin1_b     = (const float*)d_in[18];
    const float* lin2_w     = (const float*)d_in[19];
    const float* lin2_b     = (const float*)d_in[20];
    const float* lincat_w   = (const float*)d_in[21];
    const float* lincat_b   = (const float*)d_in[22];
    const float* norm_w     = (const float*)d_in[23];
    const float* norm_b     = (const float*)d_in[24];
    const float* norm_ms    = (const float*)d_in[25];
    const float* lins_w     = (const float*)d_in[26];
    const float* lins_b     = (const float*)d_in[27];
    const float* final_w    = (const float*)d_in[28];
    const float* final_b    = (const float*)d_in[29];
    float* out = (float*)d_out;

    const int* src = edge_index;        // edge_index[0, :]
    const int* dst = edge_index + EE;   // edge_index[1, :]

    float *xh, *agg1, *agg2, *tmp, *h1, *h2, *hA, *hB;
    cudaGetSymbolAddress((void**)&xh,   g_xh);
    cudaGetSymbolAddress((void**)&agg1, g_agg1);
    cudaGetSymbolAddress((void**)&agg2, g_agg2);
    cudaGetSymbolAddress((void**)&tmp,  g_tmp);
    cudaGetSymbolAddress((void**)&h1,   g_h1);
    cudaGetSymbolAddress((void**)&h2,   g_h2);
    cudaGetSymbolAddress((void**)&hA,   g_hA);
    cudaGetSymbolAddress((void**)&hB,   g_hB);

    // dynamic smem sizes
    const int NG1  = (16384 + 128*20) * 4;                         // 73.0 KB
    const int NG2  = (32768 + 2*128*20) * 4;                       // 148  KB
    const int E147 = (FF1*64 + 8192 + FF1*36 + 64*36) * 4 + 64*4;  // ~98.7 KB
    const int E21  = (FF2*64 + 8192 + FF2*36 + 64*36) * 4 + 64*4;  // ~50.7 KB

    set_smem((const void*)node_gemm<false,true ,false>, NG1);
    set_smem((const void*)node_gemm<false,true ,true >, NG1);
    set_smem((const void*)node_gemm<false,false,false>, NG1);
    set_smem((const void*)node_gemm<true ,false,false>, NG2);
    set_smem((const void*)node_gemm<true ,false,true >, NG2);
    set_smem((const void*)edge_msg2<FF1>, E147);
    set_smem((const void*)edge_msg2<FF2>, E21);

    const int NG_GRID = (NN + 15) / 16;     // 3125
    const int EL_GRID = (NN*HH + 255) / 256;
    const int GH_GRID = (GG*HH + 255) / 256;
    const int NTILES  = EE / 32;            // 31250

    // 0) zero accumulators
    zero_bufs_kernel<<<EL_GRID, 256>>>();

    // 1) xh = swish(x @ lin_w + lin_b)
    node_gemm<false,true,false><<<NG_GRID, 256, NG1>>>(
        x, lin_w, nullptr, nullptr, lin_b, nullptr, xh, NN);

    // 2) edge messages + scatter-add (register-blocked, 32 edges/tile)
    edge_msg2<FF1><<<296, 256, E147>>>(feature1, f1_w1, f1_w2, xh, src, dst, agg1, NTILES);
    edge_msg2<FF2><<<592, 256, E21 >>>(feature2, f2_w1, f2_w2, xh, src, dst, agg2, NTILES);

    // 3) conv1: tmp = agg1@rel + xh@root + rel_b ; h1 = swish(tmp@lin1 + b1)
    node_gemm<true,false,false><<<NG_GRID, 256, NG2>>>(
        agg1, c1_rel_w, xh, c1_root_w, c1_rel_b, nullptr, tmp, NN);
    node_gemm<false,true,false><<<NG_GRID, 256, NG1>>>(
        tmp, lin1_w, nullptr, nullptr, lin1_b, nullptr, h1, NN);

    // 4) conv2
    node_gemm<true,false,false><<<NG_GRID, 256, NG2>>>(
        agg2, c2_rel_w, xh, c2_root_w, c2_rel_b, nullptr, tmp, NN);
    node_gemm<false,true,false><<<NG_GRID, 256, NG1>>>(
        tmp, lin2_w, nullptr, nullptr, lin2_b, nullptr, h2, NN);

    // 5) hA = h1@Wtop + h2@Wbot + lincat_b + xh
    node_gemm<true,false,true><<<NG_GRID, 256, NG2>>>(
        h1, lincat_w, h2, lincat_w + 128*128, lincat_b, xh, hA, NN);

    // 6) residual stack: h = swish(h@Wi + bi) + h   (x3)
    node_gemm<false,true,true><<<NG_GRID, 256, NG1>>>(
        hA, lins_w + 0*16384, nullptr, nullptr, lins_b + 0*128, hA, hB, NN);
    node_gemm<false,true,true><<<NG_GRID, 256, NG1>>>(
        hB, lins_w + 1*16384, nullptr, nullptr, lins_b + 1*128, hB, hA, NN);
    node_gemm<false,true,true><<<NG_GRID, 256, NG1>>>(
        hA, lins_w + 2*16384, nullptr, nullptr, lins_b + 2*128, hA, hB, NN);

    // 7) GraphNorm on hB
    gn_accum <<<EL_GRID, 256>>>(hB, batch);
    gn_mean  <<<GH_GRID, 256>>>();
    gn_center<<<EL_GRID, 256>>>(hB, batch, norm_ms, h1);   // h1 := centered
    gn_inv   <<<GH_GRID, 256>>>();
    gn_apply <<<EL_GRID, 256>>>(h1, batch, norm_w, norm_b, hA);

    // 8) out = hA @ final_w + final_b
    node_gemm<false,false,false><<<NG_GRID, 256, NG1>>>(
        hA, final_w, nullptr, nullptr, final_b, nullptr, out, NN);
}